// round 6
// baseline (speedup 1.0000x reference)
#include <cuda_runtime.h>
#include <cuda_bf16.h>
#include <cstdint>

// ---------------------------------------------------------------------------
// Problem constants
// ---------------------------------------------------------------------------
#define N_TOK   65536
#define C_CODES 2048
#define D       64
#define KEXT    192                  // [ah | ah | al] x [eh | el | eh]
#define M_TILE  128
#define N_TILE  64                   // codes per chunk
#define NCHUNK  (C_CODES / N_TILE)   // 32
#define KSTEPS  (KEXT / 16)          // 12
#define MARGIN  0.05f

#define DECAY_F 0.8f
#define OMD_F   0.2f
#define EPS_F   1e-5f

// smem geometry: rows padded to 200 bf16 = 400 B (stride % 128 == 16 -> ldmatrix conflict-free)
#define RSTRIDE      400
#define A_BYTES      (M_TILE * RSTRIDE)      // 51200
#define BCH_BYTES    (N_TILE * RSTRIDE)      // 25600
#define SMEM_B_OFF   A_BYTES
#define SMEM_E2_OFF  (A_BYTES + 4 * BCH_BYTES)   // 153600
#define SMEM_DYN     (SMEM_E2_OFF + C_CODES * 4) // 161792

// Output layout (floats), reference return order
#define OFF_Q    0
#define OFF_IND  4194304
#define OFF_NE   4259840
#define OFF_NCS  4390912
#define OFF_NEA  4392960

// ---------------------------------------------------------------------------
// Device scratch
// ---------------------------------------------------------------------------
__device__ __nv_bfloat16 g_B[(size_t)C_CODES * KEXT]; // 786 KB, unpadded
__device__ float g_e2[C_CODES];
__device__ int   g_ind[N_TOK];
__device__ float g_counts[C_CODES];
__device__ float g_sum[C_CODES * D];
__device__ int   g_namb;
__device__ int   g_amb[N_TOK];

// ---------------------------------------------------------------------------
// PTX helpers (all baseline sm_80-era -> safe on plain sm_103 target)
// ---------------------------------------------------------------------------
__device__ __forceinline__ uint32_t smem_u32(const void* p) {
    return (uint32_t)__cvta_generic_to_shared(p);
}
__device__ __forceinline__ void cp16(uint32_t saddr, const void* g) {
    asm volatile("cp.async.cg.shared.global [%0], [%1], 16;" :: "r"(saddr), "l"(g));
}
__device__ __forceinline__ void cp_commit() {
    asm volatile("cp.async.commit_group;" ::: "memory");
}
template <int NN> __device__ __forceinline__ void cp_wait() {
    asm volatile("cp.async.wait_group %0;" :: "n"(NN) : "memory");
}
__device__ __forceinline__ void ldsm4(uint32_t* r, uint32_t addr) {
    asm volatile("ldmatrix.sync.aligned.m8n8.x4.shared.b16 {%0,%1,%2,%3}, [%4];"
                 : "=r"(r[0]), "=r"(r[1]), "=r"(r[2]), "=r"(r[3]) : "r"(addr));
}
__device__ __forceinline__ void mma16816(float* d, const uint32_t* a,
                                         uint32_t b0, uint32_t b1) {
    asm volatile(
        "mma.sync.aligned.m16n8k16.row.col.f32.bf16.bf16.f32 "
        "{%0,%1,%2,%3}, {%4,%5,%6,%7}, {%8,%9}, {%0,%1,%2,%3};"
        : "+f"(d[0]), "+f"(d[1]), "+f"(d[2]), "+f"(d[3])
        : "r"(a[0]), "r"(a[1]), "r"(a[2]), "r"(a[3]), "r"(b0), "r"(b1));
}
__device__ __forceinline__ void upd(float& best, float& b2, int& bi,
                                    float s, int c) {
    if (s < best) { b2 = best; best = s; bi = c; }
    else if (s < b2) { b2 = s; }
}

// ---------------------------------------------------------------------------
// k_zero
// ---------------------------------------------------------------------------
__global__ void k_zero() {
    int i = blockIdx.x * blockDim.x + threadIdx.x;
    if (i == 0) g_namb = 0;
    if (i < C_CODES) g_counts[i] = 0.0f;
    if (i < C_CODES * D) g_sum[i] = 0.0f;
}

// ---------------------------------------------------------------------------
// k_prep_b: B row = [eh | el | eh] bf16, e2 = sum e^2 fp32. One warp per code.
// ---------------------------------------------------------------------------
__global__ void k_prep_b(const float* __restrict__ emb) {
    int c = (blockIdx.x * blockDim.x + threadIdx.x) >> 5;
    int lane = threadIdx.x & 31;
    if (c >= C_CODES) return;
    float2 v = *(const float2*)(emb + (size_t)c * D + lane * 2);
    __nv_bfloat16 h0 = __float2bfloat16(v.x), h1 = __float2bfloat16(v.y);
    __nv_bfloat16 l0 = __float2bfloat16(v.x - __bfloat162float(h0));
    __nv_bfloat16 l1 = __float2bfloat16(v.y - __bfloat162float(h1));
    float sq = v.x * v.x + v.y * v.y;
    #pragma unroll
    for (int m = 16; m >= 1; m >>= 1)
        sq += __shfl_xor_sync(0xFFFFFFFFu, sq, m);
    __nv_bfloat162 hh; hh.x = h0; hh.y = h1;
    __nv_bfloat162 ll; ll.x = l0; ll.y = l1;
    __nv_bfloat162* base = (__nv_bfloat162*)(g_B + (size_t)c * KEXT);
    base[lane] = hh; base[32 + lane] = ll; base[64 + lane] = hh;
    if (lane == 0) g_e2[c] = sq;
}

// ---------------------------------------------------------------------------
// k_mma: HMMA (mma.sync bf16) split-GEMM + fused argmin with margin detect.
// CTA = 256 thr = 8 warps in a 4(m) x 2(n) grid. M=128, chunks of N=64.
// ---------------------------------------------------------------------------
__device__ __forceinline__ void issue_b(uint32_t dst_s,
                                        const __nv_bfloat16* src, int tid) {
    // 64 rows x 24 float4 (384B valid of 400B row)
    #pragma unroll
    for (int it = 0; it < 6; it++) {
        int i = tid + it * 256;            // 1536 total
        int n = i / 24, q = i - n * 24;
        cp16(dst_s + n * RSTRIDE + q * 16, src + (size_t)n * KEXT + q * 8);
    }
}

extern __shared__ char smraw[];

__global__ __launch_bounds__(256, 1) void k_mma(const float* __restrict__ x) {
    uint32_t base = smem_u32(smraw);
    uint32_t A_s  = base;
    uint32_t B_s  = base + SMEM_B_OFF;
    uint32_t E2_s = base + SMEM_E2_OFF;
    float* e2f = (float*)(smraw + SMEM_E2_OFF);

    __shared__ float s_bst[2][M_TILE];
    __shared__ float s_b2 [2][M_TILE];
    __shared__ int   s_bi [2][M_TILE];

    int tid = threadIdx.x;
    int lane = tid & 31, wid = tid >> 5;
    int warp_m = wid >> 1, warp_n = wid & 1;
    int g   = lane >> 2;       // groupID (row within 8)
    int tig = lane & 3;        // thread-in-group (col pairs)
    int row0 = blockIdx.x * M_TILE;

    // ---- prologue: e2 + B0 (group0), B1, B2 via cp.async ----
    for (int i = tid; i < C_CODES / 4; i += 256)
        cp16(E2_s + i * 16, ((const char*)g_e2) + i * 16);
    issue_b(B_s, g_B, tid);
    cp_commit();
    issue_b(B_s + BCH_BYTES, g_B + (size_t)N_TILE * KEXT, tid);
    cp_commit();
    issue_b(B_s + 2 * BCH_BYTES, g_B + (size_t)2 * N_TILE * KEXT, tid);
    cp_commit();

    // ---- build A tile in smem: [bf16(-2x) | dup | residual], stride 400B ----
    {
        const float2* xsrc = (const float2*)(x + (size_t)row0 * D);
        for (int idx = tid; idx < M_TILE * 32; idx += 256) {
            int r = idx >> 5, c2 = idx & 31;
            float2 v = xsrc[r * 32 + c2];
            float a0 = -2.0f * v.x, a1 = -2.0f * v.y;
            __nv_bfloat16 h0 = __float2bfloat16(a0), h1 = __float2bfloat16(a1);
            __nv_bfloat16 l0 = __float2bfloat16(a0 - __bfloat162float(h0));
            __nv_bfloat16 l1 = __float2bfloat16(a1 - __bfloat162float(h1));
            __nv_bfloat162 hh; hh.x = h0; hh.y = h1;
            __nv_bfloat162 ll; ll.x = l0; ll.y = l1;
            __nv_bfloat162* rowp = (__nv_bfloat162*)(smraw + r * RSTRIDE);
            rowp[c2] = hh; rowp[32 + c2] = hh; rowp[64 + c2] = ll;
        }
    }

    // ---- ldmatrix lane address bases ----
    int lrow = lane & 15, lsel = lane >> 4;    // 16 rows, 8-col half select
    uint32_t a_addr0 = A_s + (uint32_t)(warp_m * 32 + lrow) * RSTRIDE + lsel * 16;
    uint32_t a_addr1 = a_addr0 + 16 * RSTRIDE;
    uint32_t b_off0  = (uint32_t)(warp_n * 32 + lrow) * RSTRIDE + lsel * 16;
    uint32_t b_off1  = b_off0 + 16 * RSTRIDE;

    // tracked rows: (mt,e) -> row = warp_m*32 + mt*16 + e*8 + g
    float best[4], b2[4]; int bidx[4];
    #pragma unroll
    for (int i = 0; i < 4; i++) { best[i] = 3.4e38f; b2[i] = 3.4e38f; bidx[i] = 0; }

    for (int ch = 0; ch < NCHUNK; ch++) {
        if (ch == NCHUNK - 2)      cp_wait<1>();
        else if (ch == NCHUNK - 1) cp_wait<0>();
        else                       cp_wait<2>();
        __syncthreads();
        if (ch + 3 < NCHUNK) {
            issue_b(B_s + ((ch + 3) & 3) * BCH_BYTES,
                    g_B + (size_t)(ch + 3) * N_TILE * KEXT, tid);
            cp_commit();
        }

        uint32_t bb = B_s + (ch & 3) * BCH_BYTES;
        uint32_t pb0 = bb + b_off0, pb1 = bb + b_off1;

        float acc[2][4][4];
        #pragma unroll
        for (int mt = 0; mt < 2; mt++)
            #pragma unroll
            for (int nt = 0; nt < 4; nt++)
                #pragma unroll
                for (int q = 0; q < 4; q++) acc[mt][nt][q] = 0.0f;

        #pragma unroll
        for (int ks = 0; ks < KSTEPS; ks++) {
            uint32_t A0[4], A1[4], B0[4], B1[4];
            ldsm4(A0, a_addr0 + ks * 32);
            ldsm4(A1, a_addr1 + ks * 32);
            ldsm4(B0, pb0 + ks * 32);     // regs: [nt0 b0, nt1 b0, nt0 b1, nt1 b1]
            ldsm4(B1, pb1 + ks * 32);     // ntiles 2,3
            mma16816(acc[0][0], A0, B0[0], B0[2]);
            mma16816(acc[0][1], A0, B0[1], B0[3]);
            mma16816(acc[0][2], A0, B1[0], B1[2]);
            mma16816(acc[0][3], A0, B1[1], B1[3]);
            mma16816(acc[1][0], A1, B0[0], B0[2]);
            mma16816(acc[1][1], A1, B0[1], B0[3]);
            mma16816(acc[1][2], A1, B1[0], B1[2]);
            mma16816(acc[1][3], A1, B1[1], B1[3]);
        }

        // epilogue: add e2, update running (best,b2,idx) for 4 owned rows
        #pragma unroll
        for (int nt = 0; nt < 4; nt++) {
            int c0 = ch * N_TILE + warp_n * 32 + nt * 8 + tig * 2;
            float e20 = e2f[c0], e21 = e2f[c0 + 1];
            #pragma unroll
            for (int mt = 0; mt < 2; mt++)
                #pragma unroll
                for (int e = 0; e < 2; e++) {
                    int ri = mt * 2 + e;
                    upd(best[ri], b2[ri], bidx[ri], acc[mt][nt][e * 2 + 0] + e20, c0);
                    upd(best[ri], b2[ri], bidx[ri], acc[mt][nt][e * 2 + 1] + e21, c0 + 1);
                }
        }
    }

    // ---- quad reduce (4 lanes share each row) ----
    #pragma unroll
    for (int ri = 0; ri < 4; ri++) {
        float s = best[ri], t = b2[ri]; int i = bidx[ri];
        #pragma unroll
        for (int m = 1; m <= 2; m <<= 1) {
            float so = __shfl_xor_sync(0xFFFFFFFFu, s, m);
            float to = __shfl_xor_sync(0xFFFFFFFFu, t, m);
            int   io = __shfl_xor_sync(0xFFFFFFFFu, i, m);
            float hb  = fmaxf(s, so);
            float nb2 = fminf(fminf(t, to), hb);
            if (so < s || (so == s && io < i)) { s = so; i = io; }
            t = nb2;
        }
        best[ri] = s; b2[ri] = t; bidx[ri] = i;
    }
    if (tig == 0) {
        #pragma unroll
        for (int ri = 0; ri < 4; ri++) {
            int row = warp_m * 32 + (ri >> 1) * 16 + (ri & 1) * 8 + g;
            s_bst[warp_n][row] = best[ri];
            s_b2 [warp_n][row] = b2[ri];
            s_bi [warp_n][row] = bidx[ri];
        }
    }
    __syncthreads();

    // ---- cross-warp_n merge + final write ----
    if (tid < M_TILE) {
        float sA = s_bst[0][tid], sB = s_bst[1][tid];
        float tA = s_b2[0][tid],  tB = s_b2[1][tid];
        int   iA = s_bi[0][tid],  iB = s_bi[1][tid];
        float hb  = fmaxf(sA, sB);
        float fb2 = fminf(fminf(tA, tB), hb);
        float fb; int fi;
        if (sB < sA || (sB == sA && iB < iA)) { fb = sB; fi = iB; }
        else                                  { fb = sA; fi = iA; }
        g_ind[row0 + tid] = fi;
        if (fb2 - fb <= MARGIN) {
            int sl = atomicAdd(&g_namb, 1);
            g_amb[sl] = row0 + tid;
        }
    }
}

// ---------------------------------------------------------------------------
// k_exact: exact fp32 brute-force argmin for ambiguous rows.
// ---------------------------------------------------------------------------
__global__ void k_exact(const float* __restrict__ x,
                        const float* __restrict__ emb) {
    __shared__ float xs[D];
    __shared__ float sbest[256];
    __shared__ int   sidx[256];
    int nn = g_namb;
    for (int it = blockIdx.x; it < nn; it += gridDim.x) {
        int row = g_amb[it];
        if (threadIdx.x < D) xs[threadIdx.x] = x[(size_t)row * D + threadIdx.x];
        __syncthreads();
        float best = 3.4e38f; int bi = 0;
        for (int c = threadIdx.x; c < C_CODES; c += 256) {
            float s = 0.0f;
            #pragma unroll
            for (int k = 0; k < D; k++)
                s += xs[k] * emb[(size_t)c * D + k];
            float sc = g_e2[c] - 2.0f * s;
            if (sc < best) { best = sc; bi = c; }
        }
        sbest[threadIdx.x] = best; sidx[threadIdx.x] = bi;
        __syncthreads();
        for (int off = 128; off >= 1; off >>= 1) {
            if (threadIdx.x < off) {
                float o = sbest[threadIdx.x + off];
                int  oi = sidx[threadIdx.x + off];
                if (o < sbest[threadIdx.x] ||
                    (o == sbest[threadIdx.x] && oi < sidx[threadIdx.x])) {
                    sbest[threadIdx.x] = o; sidx[threadIdx.x] = oi;
                }
            }
            __syncthreads();
        }
        if (threadIdx.x == 0) g_ind[row] = sidx[0];
        __syncthreads();
    }
}

// ---------------------------------------------------------------------------
// k_scatter: gather quantize + embed_ind + scatter counts/sums.
// ---------------------------------------------------------------------------
__global__ void k_scatter(const float* __restrict__ x,
                          const float* __restrict__ emb,
                          float* __restrict__ out) {
    int row  = (blockIdx.x * blockDim.x + threadIdx.x) >> 5;
    int lane = threadIdx.x & 31;
    if (row >= N_TOK) return;
    int idx = g_ind[row];

    float2 q = *(const float2*)(emb + (size_t)idx * D + lane * 2);
    *(float2*)(out + OFF_Q + (size_t)row * D + lane * 2) = q;

    float2 xv = *(const float2*)(x + (size_t)row * D + lane * 2);
    atomicAdd(g_sum + (size_t)idx * D + lane * 2,     xv.x);
    atomicAdd(g_sum + (size_t)idx * D + lane * 2 + 1, xv.y);

    if (lane == 0) {
        atomicAdd(g_counts + idx, 1.0f);
        out[OFF_IND + row] = (float)idx;
    }
}

// ---------------------------------------------------------------------------
// k_final: EMA + laplace smoothing + renormalize.
// ---------------------------------------------------------------------------
__global__ __launch_bounds__(1024)
void k_final(const float* __restrict__ cs,
             const float* __restrict__ ea,
             float* __restrict__ out) {
    __shared__ float s_ncs[C_CODES];
    __shared__ float s_red[32];
    int tid = threadIdx.x;

    float local = 0.0f;
    for (int c = tid; c < C_CODES; c += 1024) {
        float v = cs[c] * DECAY_F + g_counts[c] * OMD_F;
        s_ncs[c] = v;
        out[OFF_NCS + c] = v;
        local += v;
    }
    #pragma unroll
    for (int m = 16; m >= 1; m >>= 1)
        local += __shfl_xor_sync(0xFFFFFFFFu, local, m);
    if ((tid & 31) == 0) s_red[tid >> 5] = local;
    __syncthreads();
    if (tid < 32) {
        float v = s_red[tid];
        #pragma unroll
        for (int m = 16; m >= 1; m >>= 1)
            v += __shfl_xor_sync(0xFFFFFFFFu, v, m);
        if (tid == 0) s_red[0] = v;
    }
    __syncthreads();
    float tot   = s_red[0];
    float denom = tot + (float)C_CODES * EPS_F;

    for (int i = tid; i < C_CODES * D; i += 1024) {
        int c = i >> 6;
        float nea = ea[i] * DECAY_F + g_sum[i] * OMD_F;
        out[OFF_NEA + i] = nea;
        float sm = (s_ncs[c] + EPS_F) / denom * tot;
        out[OFF_NE + i] = nea / sm;
    }
}

// ---------------------------------------------------------------------------
// kernel_launch
// ---------------------------------------------------------------------------
extern "C" void kernel_launch(void* const* d_in, const int* in_sizes, int n_in,
                              void* d_out, int out_size) {
    (void)in_sizes; (void)n_in; (void)out_size;
    const float* x   = (const float*)d_in[0];
    const float* emb = (const float*)d_in[1];
    const float* cs  = (const float*)d_in[2];
    const float* ea  = (const float*)d_in[3];
    float* out = (float*)d_out;

    cudaFuncSetAttribute(k_mma, cudaFuncAttributeMaxDynamicSharedMemorySize,
                         SMEM_DYN);

    k_zero<<<512, 256>>>();
    k_prep_b<<<256, 256>>>(emb);
    k_mma<<<N_TOK / M_TILE, 256, SMEM_DYN>>>(x);
    k_exact<<<256, 256>>>(x, emb);
    k_scatter<<<(N_TOK * 32) / 256, 256>>>(x, emb, out);
    k_final<<<1, 1024>>>(cs, ea, out);
}

// round 7
// speedup vs baseline: 3.0669x; 3.0669x over previous
#include <cuda_runtime.h>
#include <cuda_bf16.h>
#include <cstdint>

// ---------------------------------------------------------------------------
// Problem constants
// ---------------------------------------------------------------------------
#define N_TOK   65536
#define C_CODES 2048
#define D       64
#define KEXT    208                  // [ah|ah|al|1,1,0..] x [eh|el|eh|e2h,e2l,0..]
#define M_TILE  128
#define N_TILE  64                   // codes per chunk
#define NCHUNK  (C_CODES / N_TILE)   // 32
#define KSTEPS  (KEXT / 16)          // 13
#define MARGIN  0.02f

#define DECAY_F 0.8f
#define OMD_F   0.2f
#define EPS_F   1e-5f

// smem row stride 432 B (108 words ≡ 12 mod 32 -> ldmatrix conflict-free)
#define RSTRIDE      432
#define A_BYTES      (M_TILE * RSTRIDE)      // 55296
#define BCH_BYTES    (N_TILE * RSTRIDE)      // 27648
#define SMEM_B_OFF   A_BYTES
#define SMEM_DYN     (A_BYTES + 2 * BCH_BYTES)   // 110592 -> 2 CTAs/SM

// k_exact smem
#define EX_RS        68              // padded floats per code row
#define EX_SMEM      (256*EX_RS*4 + 32*64*4 + 256*4 + 128)  // 78976

// Output layout (floats), reference return order
#define OFF_Q    0
#define OFF_IND  4194304
#define OFF_NE   4259840
#define OFF_NCS  4390912
#define OFF_NEA  4392960

// ---------------------------------------------------------------------------
// Device scratch
// ---------------------------------------------------------------------------
__device__ __nv_bfloat16 g_B[(size_t)C_CODES * KEXT];
__device__ float g_e2[C_CODES];
__device__ int   g_ind[N_TOK];
__device__ float g_counts[C_CODES];
__device__ float g_sum[C_CODES * D];
__device__ int   g_namb;
__device__ int   g_amb[N_TOK];
__device__ unsigned long long g_bestpack[N_TOK];

// ---------------------------------------------------------------------------
// PTX helpers (baseline sm_80-era only — safe on plain sm_103 target)
// ---------------------------------------------------------------------------
__device__ __forceinline__ uint32_t smem_u32(const void* p) {
    return (uint32_t)__cvta_generic_to_shared(p);
}
__device__ __forceinline__ void cp16(uint32_t saddr, const void* g) {
    asm volatile("cp.async.cg.shared.global [%0], [%1], 16;" :: "r"(saddr), "l"(g));
}
__device__ __forceinline__ void cp_commit() {
    asm volatile("cp.async.commit_group;" ::: "memory");
}
template <int NN> __device__ __forceinline__ void cp_wait() {
    asm volatile("cp.async.wait_group %0;" :: "n"(NN) : "memory");
}
__device__ __forceinline__ void ldsm4(uint32_t* r, uint32_t addr) {
    asm volatile("ldmatrix.sync.aligned.m8n8.x4.shared.b16 {%0,%1,%2,%3}, [%4];"
                 : "=r"(r[0]), "=r"(r[1]), "=r"(r[2]), "=r"(r[3]) : "r"(addr));
}
__device__ __forceinline__ void mma16816(float* d, const uint32_t* a,
                                         uint32_t b0, uint32_t b1) {
    asm volatile(
        "mma.sync.aligned.m16n8k16.row.col.f32.bf16.bf16.f32 "
        "{%0,%1,%2,%3}, {%4,%5,%6,%7}, {%8,%9}, {%0,%1,%2,%3};"
        : "+f"(d[0]), "+f"(d[1]), "+f"(d[2]), "+f"(d[3])
        : "r"(a[0]), "r"(a[1]), "r"(a[2]), "r"(a[3]), "r"(b0), "r"(b1));
}

// ---------------------------------------------------------------------------
// k_zero
// ---------------------------------------------------------------------------
__global__ void k_zero() {
    int i = blockIdx.x * blockDim.x + threadIdx.x;
    if (i == 0) g_namb = 0;
    if (i < C_CODES) g_counts[i] = 0.0f;
    if (i < C_CODES * D) g_sum[i] = 0.0f;
    if (i < N_TOK) g_bestpack[i] = 0xFFFFFFFFFFFFFFFFull;
}

// ---------------------------------------------------------------------------
// k_prep_b: B row = [eh | el | eh | e2h,e2l, 0...] bf16; e2 fp32 for k_exact.
// ---------------------------------------------------------------------------
__global__ void k_prep_b(const float* __restrict__ emb) {
    int c = (blockIdx.x * blockDim.x + threadIdx.x) >> 5;
    int lane = threadIdx.x & 31;
    if (c >= C_CODES) return;
    float2 v = *(const float2*)(emb + (size_t)c * D + lane * 2);
    __nv_bfloat16 h0 = __float2bfloat16(v.x), h1 = __float2bfloat16(v.y);
    __nv_bfloat16 l0 = __float2bfloat16(v.x - __bfloat162float(h0));
    __nv_bfloat16 l1 = __float2bfloat16(v.y - __bfloat162float(h1));
    float sq = v.x * v.x + v.y * v.y;
    #pragma unroll
    for (int m = 16; m >= 1; m >>= 1)
        sq += __shfl_xor_sync(0xFFFFFFFFu, sq, m);
    __nv_bfloat162 hh; hh.x = h0; hh.y = h1;
    __nv_bfloat162 ll; ll.x = l0; ll.y = l1;
    __nv_bfloat162* base = (__nv_bfloat162*)(g_B + (size_t)c * KEXT);
    base[lane] = hh; base[32 + lane] = ll; base[64 + lane] = hh;
    if (lane == 0) {
        __nv_bfloat16 s2h = __float2bfloat16(sq);
        __nv_bfloat16 s2l = __float2bfloat16(sq - __bfloat162float(s2h));
        __nv_bfloat162 z; z.x = __float2bfloat16(0.f); z.y = z.x;
        __nv_bfloat162 e2p; e2p.x = s2h; e2p.y = s2l;
        base[96] = e2p;
        #pragma unroll
        for (int q = 97; q < 104; q++) base[q] = z;
        g_e2[c] = sq;
    }
}

// ---------------------------------------------------------------------------
// k_mma: HMMA split-GEMM (K=208, e2 folded) + fused argmin, margin detect.
// CTA = 256 thr (8 warps, 4m x 2n). 2 CTAs/SM. Double-buffered B.
// ---------------------------------------------------------------------------
__device__ __forceinline__ void issue_b(uint32_t dst, const __nv_bfloat16* src,
                                        int tid) {
    // 64 rows x 26 float4 (416 valid bytes of 432 row)
    #pragma unroll
    for (int it = 0; it < 7; it++) {
        int i = tid + it * 256;
        if (i < 64 * 26) {
            int n = i / 26, q = i - n * 26;
            cp16(dst + n * RSTRIDE + q * 16, src + (size_t)n * KEXT + q * 8);
        }
    }
}

extern __shared__ char smraw[];

__global__ __launch_bounds__(256, 2) void k_mma(const float* __restrict__ x) {
    uint32_t A_s = smem_u32(smraw);
    uint32_t B_s = A_s + SMEM_B_OFF;

    __shared__ float s_bst[2][M_TILE];
    __shared__ float s_b2 [2][M_TILE];
    __shared__ int   s_bi [2][M_TILE];

    int tid = threadIdx.x;
    int lane = tid & 31, wid = tid >> 5;
    int warp_m = wid >> 1, warp_n = wid & 1;
    int g   = lane >> 2;
    int tig = lane & 3;
    int row0 = blockIdx.x * M_TILE;

    // prologue: B chunk 0
    issue_b(B_s, g_B, tid);
    cp_commit();

    // build A tile: [bf16(-2x)|dup|residual|1,1,0...]
    {
        const float2* xsrc = (const float2*)(x + (size_t)row0 * D);
        for (int idx = tid; idx < M_TILE * 32; idx += 256) {
            int r = idx >> 5, c2 = idx & 31;
            float2 v = xsrc[r * 32 + c2];
            float a0 = -2.0f * v.x, a1 = -2.0f * v.y;
            __nv_bfloat16 h0 = __float2bfloat16(a0), h1 = __float2bfloat16(a1);
            __nv_bfloat16 l0 = __float2bfloat16(a0 - __bfloat162float(h0));
            __nv_bfloat16 l1 = __float2bfloat16(a1 - __bfloat162float(h1));
            __nv_bfloat162 hh; hh.x = h0; hh.y = h1;
            __nv_bfloat162 ll; ll.x = l0; ll.y = l1;
            __nv_bfloat162* rowp = (__nv_bfloat162*)(smraw + r * RSTRIDE);
            rowp[c2] = hh; rowp[32 + c2] = hh; rowp[64 + c2] = ll;
        }
        // cols 192..207: [1,1, 0...]
        for (int r = tid; r < M_TILE; r += 256) {
            uint4* tailp = (uint4*)(smraw + r * RSTRIDE + 384);
            tailp[0] = make_uint4(0x3F803F80u, 0u, 0u, 0u);
            tailp[1] = make_uint4(0u, 0u, 0u, 0u);
        }
    }

    int lrow = lane & 15, lsel = lane >> 4;
    uint32_t a_addr0 = A_s + (uint32_t)(warp_m * 32 + lrow) * RSTRIDE + lsel * 16;
    uint32_t a_addr1 = a_addr0 + 16 * RSTRIDE;
    uint32_t b_off0  = (uint32_t)(warp_n * 32 + lrow) * RSTRIDE + lsel * 16;
    uint32_t b_off1  = b_off0 + 16 * RSTRIDE;

    float best[4], b2[4]; int bidx[4];
    #pragma unroll
    for (int i = 0; i < 4; i++) { best[i] = 3.4e38f; b2[i] = 3.4e38f; bidx[i] = 0; }

    for (int ch = 0; ch < NCHUNK; ch++) {
        cp_wait<0>();
        __syncthreads();
        if (ch + 1 < NCHUNK) {
            issue_b(B_s + ((ch + 1) & 1) * BCH_BYTES,
                    g_B + (size_t)(ch + 1) * N_TILE * KEXT, tid);
            cp_commit();
        }

        uint32_t bb = B_s + (ch & 1) * BCH_BYTES;
        uint32_t pb0 = bb + b_off0, pb1 = bb + b_off1;

        float acc[2][4][4];
        #pragma unroll
        for (int mt = 0; mt < 2; mt++)
            #pragma unroll
            for (int nt = 0; nt < 4; nt++)
                #pragma unroll
                for (int q = 0; q < 4; q++) acc[mt][nt][q] = 0.0f;

        #pragma unroll
        for (int ks = 0; ks < KSTEPS; ks++) {
            uint32_t A0[4], A1[4], B0[4], B1[4];
            ldsm4(A0, a_addr0 + ks * 32);
            ldsm4(A1, a_addr1 + ks * 32);
            ldsm4(B0, pb0 + ks * 32);
            ldsm4(B1, pb1 + ks * 32);
            mma16816(acc[0][0], A0, B0[0], B0[2]);
            mma16816(acc[0][1], A0, B0[1], B0[3]);
            mma16816(acc[0][2], A0, B1[0], B1[2]);
            mma16816(acc[0][3], A0, B1[1], B1[3]);
            mma16816(acc[1][0], A1, B0[0], B0[2]);
            mma16816(acc[1][1], A1, B0[1], B0[3]);
            mma16816(acc[1][2], A1, B1[0], B1[2]);
            mma16816(acc[1][3], A1, B1[1], B1[3]);
        }

        // branchless epilogue: pack 3-bit local idx into mantissa LSBs,
        // per-row-stream (m1, m2) via FMNMX chains, one unpack per chunk.
        #pragma unroll
        for (int mt = 0; mt < 2; mt++)
            #pragma unroll
            for (int e = 0; e < 2; e++) {
                int ri = mt * 2 + e;
                float m1 = 3.4e38f, m2 = 3.4e38f;
                #pragma unroll
                for (int nt = 0; nt < 4; nt++)
                    #pragma unroll
                    for (int b = 0; b < 2; b++) {
                        float s = acc[mt][nt][e * 2 + b];
                        uint32_t u = (__float_as_uint(s) & ~7u) |
                                     (uint32_t)(nt * 2 + b);
                        float sp = __uint_as_float(u);
                        m2 = fminf(m2, fmaxf(m1, sp));
                        m1 = fminf(m1, sp);
                    }
                uint32_t lu = __float_as_uint(m1) & 7u;
                int code = ch * N_TILE + warp_n * 32 +
                           (int)(lu >> 1) * 8 + tig * 2 + (int)(lu & 1);
                float hb = fmaxf(best[ri], m1);
                b2[ri] = fminf(fminf(b2[ri], m2), hb);
                if (m1 < best[ri]) { best[ri] = m1; bidx[ri] = code; }
            }
    }

    // quad reduce (4 tig lanes share each row)
    #pragma unroll
    for (int ri = 0; ri < 4; ri++) {
        float s = best[ri], t = b2[ri]; int i = bidx[ri];
        #pragma unroll
        for (int m = 1; m <= 2; m <<= 1) {
            float so = __shfl_xor_sync(0xFFFFFFFFu, s, m);
            float to = __shfl_xor_sync(0xFFFFFFFFu, t, m);
            int   io = __shfl_xor_sync(0xFFFFFFFFu, i, m);
            float hb  = fmaxf(s, so);
            float nb2 = fminf(fminf(t, to), hb);
            if (so < s || (so == s && io < i)) { s = so; i = io; }
            t = nb2;
        }
        best[ri] = s; b2[ri] = t; bidx[ri] = i;
    }
    if (tig == 0) {
        #pragma unroll
        for (int ri = 0; ri < 4; ri++) {
            int row = warp_m * 32 + (ri >> 1) * 16 + (ri & 1) * 8 + g;
            s_bst[warp_n][row] = best[ri];
            s_b2 [warp_n][row] = b2[ri];
            s_bi [warp_n][row] = bidx[ri];
        }
    }
    __syncthreads();

    if (tid < M_TILE) {
        float sA = s_bst[0][tid], sB = s_bst[1][tid];
        float tA = s_b2[0][tid],  tB = s_b2[1][tid];
        int   iA = s_bi[0][tid],  iB = s_bi[1][tid];
        float hb  = fmaxf(sA, sB);
        float fb2 = fminf(fminf(tA, tB), hb);
        float fb; int fi;
        if (sB < sA || (sB == sA && iB < iA)) { fb = sB; fi = iB; }
        else                                  { fb = sA; fi = iA; }
        g_ind[row0 + tid] = fi;
        if (fb2 - fb <= MARGIN) {
            int sl = atomicAdd(&g_namb, 1);
            g_amb[sl] = row0 + tid;
        }
    }
}

// ---------------------------------------------------------------------------
// k_exact: exact fp32 argmin for ambiguous rows. Tiled: 32 rows x 256 codes
// per task, codes/x in smem, coalesced loads, atomicMin(u64) merge.
// ---------------------------------------------------------------------------
__global__ __launch_bounds__(256) void k_exact(const float* __restrict__ x,
                                               const float* __restrict__ emb) {
    extern __shared__ float esm[];
    float* s_e  = esm;                       // 256 x EX_RS
    float* s_x  = esm + 256 * EX_RS;         // 32 x 64
    float* s_e2 = s_x + 32 * 64;             // 256
    int*   s_rid = (int*)(s_e2 + 256);       // 32

    int nn = g_namb;
    int ntasks = ((nn + 31) >> 5) * 8;
    int tid = threadIdx.x;

    for (int task = blockIdx.x; task < ntasks; task += gridDim.x) {
        int rg = task >> 3, cc = task & 7;
        __syncthreads();
        if (tid < 32) {
            int ai = rg * 32 + tid;
            s_rid[tid] = (ai < nn) ? g_amb[ai] : -1;
        }
        for (int i = tid; i < 256 * 16; i += 256) {
            int c = i >> 4, q = i & 15;
            float4 v = *(const float4*)(emb + ((size_t)(cc * 256 + c)) * 64 + q * 4);
            *(float4*)(s_e + c * EX_RS + q * 4) = v;
        }
        s_e2[tid] = g_e2[cc * 256 + tid];
        __syncthreads();
        for (int i = tid; i < 32 * 16; i += 256) {
            int r = i >> 4, q = i & 15;
            int rid = s_rid[r];
            float4 v = (rid >= 0)
                ? *(const float4*)(x + (size_t)rid * 64 + q * 4)
                : make_float4(0.f, 0.f, 0.f, 0.f);
            *(float4*)(s_x + r * 64 + q * 4) = v;
        }
        __syncthreads();

        int row = tid >> 3, cl = tid & 7;
        int rid = s_rid[row];
        if (rid >= 0) {
            float dots[32];
            #pragma unroll
            for (int j = 0; j < 32; j++) dots[j] = 0.f;
            #pragma unroll
            for (int kt = 0; kt < 4; kt++) {
                float xr[16];
                #pragma unroll
                for (int q = 0; q < 4; q++) {
                    float4 v = *(const float4*)(s_x + row * 64 + kt * 16 + q * 4);
                    xr[q*4] = v.x; xr[q*4+1] = v.y; xr[q*4+2] = v.z; xr[q*4+3] = v.w;
                }
                #pragma unroll
                for (int j = 0; j < 32; j++) {
                    const float* ep = s_e + (cl + 8 * j) * EX_RS + kt * 16;
                    #pragma unroll
                    for (int q = 0; q < 4; q++) {
                        float4 ev = *(const float4*)(ep + q * 4);
                        dots[j] += xr[q*4]*ev.x + xr[q*4+1]*ev.y +
                                   xr[q*4+2]*ev.z + xr[q*4+3]*ev.w;
                    }
                }
            }
            float best = 3.4e38f; int bi = 0x7FFFFFFF;
            #pragma unroll
            for (int j = 0; j < 32; j++) {
                int c = cl + 8 * j;
                float sc = s_e2[c] - 2.0f * dots[j];
                int gc = cc * 256 + c;
                if (sc < best || (sc == best && gc < bi)) { best = sc; bi = gc; }
            }
            uint32_t u = __float_as_uint(best);
            u ^= (u & 0x80000000u) ? 0xFFFFFFFFu : 0x80000000u;
            unsigned long long pk =
                ((unsigned long long)u << 32) | (unsigned)bi;
            atomicMin(&g_bestpack[rid], pk);
        }
    }
}

// ---------------------------------------------------------------------------
// k_fix: commit exact argmin for ambiguous rows
// ---------------------------------------------------------------------------
__global__ void k_fix() {
    int nn = g_namb;
    for (int i = blockIdx.x * blockDim.x + threadIdx.x; i < nn;
         i += gridDim.x * blockDim.x) {
        int row = g_amb[i];
        g_ind[row] = (int)(g_bestpack[row] & 0xFFFFFFFFull);
    }
}

// ---------------------------------------------------------------------------
// k_scatter: gather quantize + embed_ind + scatter counts/sums.
// ---------------------------------------------------------------------------
__global__ void k_scatter(const float* __restrict__ x,
                          const float* __restrict__ emb,
                          float* __restrict__ out) {
    int row  = (blockIdx.x * blockDim.x + threadIdx.x) >> 5;
    int lane = threadIdx.x & 31;
    if (row >= N_TOK) return;
    int idx = g_ind[row];

    float2 q = *(const float2*)(emb + (size_t)idx * D + lane * 2);
    *(float2*)(out + OFF_Q + (size_t)row * D + lane * 2) = q;

    float2 xv = *(const float2*)(x + (size_t)row * D + lane * 2);
    atomicAdd(g_sum + (size_t)idx * D + lane * 2,     xv.x);
    atomicAdd(g_sum + (size_t)idx * D + lane * 2 + 1, xv.y);

    if (lane == 0) {
        atomicAdd(g_counts + idx, 1.0f);
        out[OFF_IND + row] = (float)idx;
    }
}

// ---------------------------------------------------------------------------
// k_final: EMA + laplace smoothing + renormalize.
// ---------------------------------------------------------------------------
__global__ __launch_bounds__(1024)
void k_final(const float* __restrict__ cs,
             const float* __restrict__ ea,
             float* __restrict__ out) {
    __shared__ float s_ncs[C_CODES];
    __shared__ float s_red[32];
    int tid = threadIdx.x;

    float local = 0.0f;
    for (int c = tid; c < C_CODES; c += 1024) {
        float v = cs[c] * DECAY_F + g_counts[c] * OMD_F;
        s_ncs[c] = v;
        out[OFF_NCS + c] = v;
        local += v;
    }
    #pragma unroll
    for (int m = 16; m >= 1; m >>= 1)
        local += __shfl_xor_sync(0xFFFFFFFFu, local, m);
    if ((tid & 31) == 0) s_red[tid >> 5] = local;
    __syncthreads();
    if (tid < 32) {
        float v = s_red[tid];
        #pragma unroll
        for (int m = 16; m >= 1; m >>= 1)
            v += __shfl_xor_sync(0xFFFFFFFFu, v, m);
        if (tid == 0) s_red[0] = v;
    }
    __syncthreads();
    float tot   = s_red[0];
    float denom = tot + (float)C_CODES * EPS_F;

    for (int i = tid; i < C_CODES * D; i += 1024) {
        int c = i >> 6;
        float nea = ea[i] * DECAY_F + g_sum[i] * OMD_F;
        out[OFF_NEA + i] = nea;
        float sm = (s_ncs[c] + EPS_F) / denom * tot;
        out[OFF_NE + i] = nea / sm;
    }
}

// ---------------------------------------------------------------------------
// kernel_launch
// ---------------------------------------------------------------------------
extern "C" void kernel_launch(void* const* d_in, const int* in_sizes, int n_in,
                              void* d_out, int out_size) {
    (void)in_sizes; (void)n_in; (void)out_size;
    const float* x   = (const float*)d_in[0];
    const float* emb = (const float*)d_in[1];
    const float* cs  = (const float*)d_in[2];
    const float* ea  = (const float*)d_in[3];
    float* out = (float*)d_out;

    cudaFuncSetAttribute(k_mma, cudaFuncAttributeMaxDynamicSharedMemorySize,
                         SMEM_DYN);
    cudaFuncSetAttribute(k_exact, cudaFuncAttributeMaxDynamicSharedMemorySize,
                         EX_SMEM);

    k_zero<<<512, 256>>>();
    k_prep_b<<<256, 256>>>(emb);
    k_mma<<<N_TOK / M_TILE, 256, SMEM_DYN>>>(x);
    k_exact<<<1024, 256, EX_SMEM>>>(x, emb);
    k_fix<<<64, 256>>>();
    k_scatter<<<(N_TOK * 32) / 256, 256>>>(x, emb, out);
    k_final<<<1, 1024>>>(cs, ea, out);
}